// round 6
// baseline (speedup 1.0000x reference)
#include <cuda_runtime.h>
#include <math.h>
#include <stdint.h>

#define NMAX 50000
#define EMAX 800000
#define D    128
#define SAP  68            // A smem row pad (floats)

// ---------------- scratch (static device globals; no allocation) -------------
__device__ int   g_deg_out[NMAX];
__device__ int   g_deg_in [NMAX];
__device__ float g_ns[NMAX];
__device__ float g_nd[NMAX];
__device__ int   g_row_off[NMAX + 1];
__device__ int   g_cursor[NMAX];
__device__ int   g_csr_src[EMAX];
__device__ int   g_bsum[256];
__device__ int   g_boff[256];
__device__ int   g_total;
__device__ float g_y [NMAX * D];        // post-GEMM features (gather source)
__device__ float g_fa[NMAX * D];        // ping
__device__ float g_fb[NMAX * D];        // pong
// W^T in mma.sync B-fragment-major order: [kk(16)][nb(16)][lane(32)][2]
__device__ float g_wt_hi[5 * D * D];
__device__ float g_wt_lo[5 * D * D];

// ---------------- helpers ------------------------------------------------------
__device__ __forceinline__ float to_tf32(float x) {
    uint32_t u;
    asm("cvt.rna.tf32.f32 %0, %1;" : "=r"(u) : "f"(x));
    return __uint_as_float(u);
}

#define MMA_TF32(c, a, b0, b1)                                                  \
    asm volatile("mma.sync.aligned.m16n8k8.row.col.f32.tf32.tf32.f32 "          \
        "{%0,%1,%2,%3}, {%4,%5,%6,%7}, {%8,%9}, {%0,%1,%2,%3};"                 \
        : "+f"((c)[0]), "+f"((c)[1]), "+f"((c)[2]), "+f"((c)[3])                 \
        : "r"((a)[0]), "r"((a)[1]), "r"((a)[2]), "r"((a)[3]),                    \
          "r"(b0), "r"(b1))

// ---------------- graph preprocessing ----------------------------------------
__global__ void zero_kernel(int n) {
    int i = blockIdx.x * blockDim.x + threadIdx.x;
    if (i < n) { g_deg_out[i] = 0; g_deg_in[i] = 0; g_cursor[i] = 0; }
}

__global__ void count_kernel(const int* __restrict__ src,
                             const int* __restrict__ dst, int e) {
    int i = blockIdx.x * blockDim.x + threadIdx.x;
    if (i < e) {
        atomicAdd(&g_deg_out[src[i]], 1);
        atomicAdd(&g_deg_in [dst[i]], 1);
    }
}

__global__ void norm_kernel(int n) {
    int i = blockIdx.x * blockDim.x + threadIdx.x;
    if (i < n) {
        int dof = g_deg_out[i]; if (dof < 1) dof = 1;
        int din = g_deg_in [i]; if (din < 1) din = 1;
        g_ns[i] = rsqrtf((float)dof);
        g_nd[i] = rsqrtf((float)din);
    }
}

__global__ void scan1_kernel(int n) {
    int tid = threadIdx.x, lane = tid & 31, warp = tid >> 5;
    int i = blockIdx.x * 256 + tid;
    int v = (i < n) ? g_deg_in[i] : 0;
    int x = v;
    #pragma unroll
    for (int off = 1; off < 32; off <<= 1) {
        int t = __shfl_up_sync(0xffffffffu, x, off);
        if (lane >= off) x += t;
    }
    __shared__ int ws[8];
    if (lane == 31) ws[warp] = x;
    __syncthreads();
    if (tid == 0) {
        int c = 0;
        #pragma unroll
        for (int j = 0; j < 8; j++) { int t = ws[j]; ws[j] = c; c += t; }
        g_bsum[blockIdx.x] = c;
    }
    __syncthreads();
    if (i < n) g_row_off[i] = ws[warp] + x - v;
}

__global__ void scan2_kernel(int nb) {
    int tid = threadIdx.x, lane = tid & 31, warp = tid >> 5;
    int v = (tid < nb) ? g_bsum[tid] : 0;
    int x = v;
    #pragma unroll
    for (int off = 1; off < 32; off <<= 1) {
        int t = __shfl_up_sync(0xffffffffu, x, off);
        if (lane >= off) x += t;
    }
    __shared__ int ws[8];
    if (lane == 31) ws[warp] = x;
    __syncthreads();
    if (tid == 0) {
        int c = 0;
        #pragma unroll
        for (int j = 0; j < 8; j++) { int t = ws[j]; ws[j] = c; c += t; }
        g_total = c;
    }
    __syncthreads();
    if (tid < nb) g_boff[tid] = ws[warp] + x - v;
}

__global__ void scan3_kernel(int n) {
    int i = blockIdx.x * blockDim.x + threadIdx.x;
    if (i < n)       g_row_off[i] += g_boff[i >> 8];
    else if (i == n) g_row_off[n]  = g_total;
}

__global__ void fill_kernel(const int* __restrict__ src,
                            const int* __restrict__ dst, int e) {
    int i = blockIdx.x * blockDim.x + threadIdx.x;
    if (i < e) {
        int d = dst[i];
        int pos = g_row_off[d] + atomicAdd(&g_cursor[d], 1);
        g_csr_src[pos] = src[i];
    }
}

__global__ void sort_kernel(int n) {
    int i = blockIdx.x * blockDim.x + threadIdx.x;
    if (i >= n) return;
    int a = g_row_off[i], b = g_row_off[i + 1];
    for (int p = a + 1; p < b; p++) {
        int key = g_csr_src[p];
        int q = p - 1;
        while (q >= a && g_csr_src[q] > key) { g_csr_src[q + 1] = g_csr_src[q]; q--; }
        g_csr_src[q + 1] = key;
    }
}

// ------- W^T split to tf32 hi/lo AND permuted to B-fragment order -------------
// frag index for element W^T[ncol][krow]:
//   nb=ncol/8, g=ncol%8, kk=krow/8, tt=krow%8, t=tt%4, j=tt/4, lane=g*4+t
//   fidx = ((kk*16+nb)*32 + lane)*2 + j
__global__ void wprep_kernel(const float* __restrict__ W0, const float* __restrict__ W1,
                             const float* __restrict__ W2, const float* __restrict__ W3,
                             const float* __restrict__ W4) {
    const float* Ws[5] = {W0, W1, W2, W3, W4};
    const float* W = Ws[blockIdx.z];
    __shared__ float t[32][33];
    int kb = blockIdx.x * 32, nb0 = blockIdx.y * 32;
    int tx = threadIdx.x, ty = threadIdx.y;
    #pragma unroll
    for (int j = 0; j < 4; j++)
        t[ty + 8 * j][tx] = W[(kb + ty + 8 * j) * D + nb0 + tx];
    __syncthreads();
    size_t base = (size_t)blockIdx.z * D * D;
    #pragma unroll
    for (int j = 0; j < 4; j++) {
        int ncol = nb0 + ty + 8 * j;
        int krow = kb + tx;
        float v = t[tx][ty + 8 * j];       // = W^T[ncol][krow]
        float hi = to_tf32(v);
        int nbk = ncol >> 3, g = ncol & 7;
        int kk = krow >> 3, tt = krow & 7;
        int tq = tt & 3, jj = tt >> 2;
        int lane = (g << 2) | tq;
        size_t fidx = base + (size_t)(((kk * 16 + nbk) * 32 + lane) * 2 + jj);
        g_wt_hi[fidx] = hi;
        g_wt_lo[fidx] = v - hi;
    }
}

// ---------------- tensor-core GEMM via mma.sync (3xTF32) ----------------------
// 256 threads = 8 warps (4x2). Block tile 128x128, warp tile 32x64.
// W^T resident in smem in fragment-major order (one LDS.64 per B frag).
__global__ __launch_bounds__(256, 1)
void gemm_mma_kernel(const float* __restrict__ x,
                     const float* __restrict__ wth,
                     const float* __restrict__ wtl,
                     float* __restrict__ y, int n) {
    extern __shared__ float sm[];
    float* sWh = sm;                       // 16384 floats
    float* sWl = sm + 16384;
    float* sAh = sm + 32768;               // 128*68 = 8704
    float* sAl = sm + 32768 + 8704;

    int tid = threadIdx.x;
    // linear copy of fragment-major W (fully coalesced float4)
    for (int idx = tid; idx < 4096; idx += 256) {
        *(float4*)(sWh + idx * 4) = *(const float4*)(wth + (size_t)idx * 4);
        *(float4*)(sWl + idx * 4) = *(const float4*)(wtl + (size_t)idx * 4);
    }

    int lane = tid & 31, wid = tid >> 5;
    int wm = wid & 3;            // warp row group (0..3) -> 32 rows each
    int wn = wid >> 2;           // warp col group (0..1) -> 64 cols each
    int g = lane >> 2, t = lane & 3;

    // per-thread fixed (row, col) slots for A chunk loads: 8 float4 each
    int prow[8], pq[8];
    #pragma unroll
    for (int j = 0; j < 8; j++) {
        int idx = tid + 256 * j;
        prow[j] = idx >> 4;
        pq[j]   = (idx & 15) * 4;
    }

    int ntiles = (n + 127) >> 7;

    for (int tile = blockIdx.x; tile < ntiles; tile += gridDim.x) {
        int r0 = tile << 7;
        float acc[2][8][4];
        #pragma unroll
        for (int mt = 0; mt < 2; mt++)
            #pragma unroll
            for (int nt = 0; nt < 8; nt++)
                #pragma unroll
                for (int j = 0; j < 4; j++) acc[mt][nt][j] = 0.f;

        // prefetch chunk 0
        float4 pf[8];
        #pragma unroll
        for (int j = 0; j < 8; j++) {
            int gr = r0 + prow[j];
            pf[j] = (gr < n) ? *(const float4*)(x + (size_t)gr * D + pq[j])
                             : make_float4(0.f, 0.f, 0.f, 0.f);
        }

        #pragma unroll
        for (int c = 0; c < 2; c++) {
            __syncthreads();   // previous chunk fully consumed (and W loaded)
            #pragma unroll
            for (int j = 0; j < 8; j++) {
                int gr = r0 + prow[j];
                float s = (gr < n) ? g_ns[gr] : 0.f;
                float4 v = pf[j];
                v.x *= s; v.y *= s; v.z *= s; v.w *= s;
                float4 h, l;
                h.x = to_tf32(v.x); l.x = v.x - h.x;
                h.y = to_tf32(v.y); l.y = v.y - h.y;
                h.z = to_tf32(v.z); l.z = v.z - h.z;
                h.w = to_tf32(v.w); l.w = v.w - h.w;
                *(float4*)(sAh + prow[j] * SAP + pq[j]) = h;
                *(float4*)(sAl + prow[j] * SAP + pq[j]) = l;
            }
            if (c == 0) {
                #pragma unroll
                for (int j = 0; j < 8; j++) {
                    int gr = r0 + prow[j];
                    pf[j] = (gr < n) ? *(const float4*)(x + (size_t)gr * D + 64 + pq[j])
                                     : make_float4(0.f, 0.f, 0.f, 0.f);
                }
            }
            __syncthreads();

            #pragma unroll
            for (int ks = 0; ks < 8; ks++) {
                int kA = ks * 8;           // col in A chunk
                int kk = c * 8 + ks;       // global k-step
                uint32_t ah[2][4], al[2][4];
                #pragma unroll
                for (int mt = 0; mt < 2; mt++) {
                    int rb = wm * 32 + mt * 16;
                    int i00 = (rb + g) * SAP + kA + t;
                    int i10 = (rb + g + 8) * SAP + kA + t;
                    ah[mt][0] = __float_as_uint(sAh[i00]);
                    ah[mt][1] = __float_as_uint(sAh[i10]);
                    ah[mt][2] = __float_as_uint(sAh[i00 + 4]);
                    ah[mt][3] = __float_as_uint(sAh[i10 + 4]);
                    al[mt][0] = __float_as_uint(sAl[i00]);
                    al[mt][1] = __float_as_uint(sAl[i10]);
                    al[mt][2] = __float_as_uint(sAl[i00 + 4]);
                    al[mt][3] = __float_as_uint(sAl[i10 + 4]);
                }
                int fb = ((kk * 16 + wn * 8) * 32 + lane) * 2;
                #pragma unroll
                for (int nt = 0; nt < 8; nt++) {
                    uint2 bh = *(const uint2*)(sWh + fb + nt * 64);
                    uint2 bl = *(const uint2*)(sWl + fb + nt * 64);
                    #pragma unroll
                    for (int mt = 0; mt < 2; mt++) {
                        MMA_TF32(acc[mt][nt], ah[mt], bh.x, bh.y);
                        MMA_TF32(acc[mt][nt], ah[mt], bl.x, bl.y);
                        MMA_TF32(acc[mt][nt], al[mt], bh.x, bh.y);
                    }
                }
            }
        }

        // epilogue: c0,c1 -> row g, cols 2t,2t+1 ; c2,c3 -> row g+8
        #pragma unroll
        for (int mt = 0; mt < 2; mt++) {
            int rlo = r0 + wm * 32 + mt * 16 + g;
            int rhi = rlo + 8;
            #pragma unroll
            for (int nt = 0; nt < 8; nt++) {
                int cb = wn * 64 + nt * 8 + 2 * t;
                if (rlo < n) {
                    float2 o = {acc[mt][nt][0], acc[mt][nt][1]};
                    *(float2*)(y + (size_t)rlo * D + cb) = o;
                }
                if (rhi < n) {
                    float2 o = {acc[mt][nt][2], acc[mt][nt][3]};
                    *(float2*)(y + (size_t)rhi * D + cb) = o;
                }
            }
        }
    }
}

// ---------------- aggregation: out = relu(nd * segsum(y[src]) + b) -----------
// 2 warps per node; each warp owns 64 columns, lane handles float2.
__global__ void agg_kernel(const float* __restrict__ y,
                           const float* __restrict__ bias,
                           float* __restrict__ out,
                           float* __restrict__ out_thr, int n) {
    int gw2 = (blockIdx.x * blockDim.x + threadIdx.x) >> 5;
    int node = gw2 >> 1;
    int lane = threadIdx.x & 31;
    if (node >= n) return;
    int coff = (gw2 & 1) * 64 + lane * 2;
    int s0 = g_row_off[node], s1 = g_row_off[node + 1];
    float2 acc = {0.f, 0.f};
    int e = s0;
    for (; e + 4 <= s1; e += 4) {
        int i0 = g_csr_src[e + 0];
        int i1 = g_csr_src[e + 1];
        int i2 = g_csr_src[e + 2];
        int i3 = g_csr_src[e + 3];
        float2 v0 = *(const float2*)(y + (size_t)i0 * D + coff);
        float2 v1 = *(const float2*)(y + (size_t)i1 * D + coff);
        float2 v2 = *(const float2*)(y + (size_t)i2 * D + coff);
        float2 v3 = *(const float2*)(y + (size_t)i3 * D + coff);
        acc.x += v0.x + v1.x + v2.x + v3.x;
        acc.y += v0.y + v1.y + v2.y + v3.y;
    }
    for (; e < s1; e++) {
        int i0 = g_csr_src[e];
        float2 v0 = *(const float2*)(y + (size_t)i0 * D + coff);
        acc.x += v0.x; acc.y += v0.y;
    }
    float ndv = g_nd[node];
    float2 bb = *(const float2*)(bias + coff);
    float2 r;
    r.x = fmaxf(acc.x * ndv + bb.x, 0.f);
    r.y = fmaxf(acc.y * ndv + bb.y, 0.f);
    *(float2*)(out + (size_t)node * D + coff) = r;
    if (out_thr) {
        float2 t;
        t.x = r.x >= 0.5f ? 1.f : 0.f;
        t.y = r.y >= 0.5f ? 1.f : 0.f;
        *(float2*)(out_thr + (size_t)node * D + coff) = t;
    }
}

// ---------------- host launcher ----------------------------------------------
extern "C" void kernel_launch(void* const* d_in, const int* in_sizes, int n_in,
                              void* d_out, int out_size) {
    const float* in_feat = (const float*)d_in[0];
    const int*   src     = (const int*)d_in[1];
    const int*   dst     = (const int*)d_in[2];
    int N = in_sizes[0] / D;
    int E = in_sizes[1];

    const float* W[5]; const float* B[5];
    int nw = 0, nb = 0;
    for (int i = 3; i < n_in; i++) {
        if (in_sizes[i] >= D * D) { if (nw < 5) W[nw++] = (const float*)d_in[i]; }
        else                      { if (nb < 5) B[nb++] = (const float*)d_in[i]; }
    }

    float* out = (float*)d_out;
    float* out_thr = (out_size >= 2 * N * D) ? out + (size_t)N * D : nullptr;

    float* fa; float* fb; float* ybuf; float* wth; float* wtl;
    cudaGetSymbolAddress((void**)&fa,   g_fa);
    cudaGetSymbolAddress((void**)&fb,   g_fb);
    cudaGetSymbolAddress((void**)&ybuf, g_y);
    cudaGetSymbolAddress((void**)&wth,  g_wt_hi);
    cudaGetSymbolAddress((void**)&wtl,  g_wt_lo);

    static cudaStream_t s2 = nullptr;
    static cudaEvent_t evA = nullptr, evB = nullptr;
    if (!s2) {
        cudaStreamCreateWithFlags(&s2, cudaStreamNonBlocking);
        cudaEventCreateWithFlags(&evA, cudaEventDisableTiming);
        cudaEventCreateWithFlags(&evB, cudaEventDisableTiming);
    }

    const int TB = 256;
    int nb_nodes = (N + TB - 1) / TB;
    int nb_edges = (E + TB - 1) / TB;
    int nscan = nb_nodes;

    // main stream: degrees (needed by both branches)
    zero_kernel <<<nb_nodes, TB>>>(N);
    count_kernel<<<nb_edges, TB>>>(src, dst, E);
    cudaEventRecord(evA, 0);

    // side stream: CSR build (needed only by agg of layer 1)
    cudaStreamWaitEvent(s2, evA, 0);
    scan1_kernel<<<nscan, 256, 0, s2>>>(N);
    scan2_kernel<<<1, 256, 0, s2>>>(nscan);
    scan3_kernel<<<(N + 1 + TB - 1) / TB, TB, 0, s2>>>(N);
    fill_kernel <<<nb_edges, TB, 0, s2>>>(src, dst, E);
    sort_kernel <<<nb_nodes, TB, 0, s2>>>(N);
    cudaEventRecord(evB, s2);

    // main stream: norms, W prep, GEMM layer 1 (overlaps CSR build)
    norm_kernel <<<nb_nodes, TB>>>(N);
    wprep_kernel<<<dim3(4, 4, 5), dim3(32, 8)>>>(W[0], W[1], W[2], W[3], W[4]);

    size_t smem = (size_t)(32768 + 2 * D * SAP) * sizeof(float);
    cudaFuncSetAttribute(gemm_mma_kernel,
                         cudaFuncAttributeMaxDynamicSharedMemorySize, (int)smem);
    int ntiles = (N + 127) / 128;
    int ggrid = 148;
    if (ggrid > ntiles) ggrid = ntiles;
    int agrid = (N * 64 + TB - 1) / TB;   // 2 warps per node

    const float* cur = in_feat;
    for (int l = 0; l < 5; l++) {
        gemm_mma_kernel<<<ggrid, 256, smem>>>(cur, wth + (size_t)l * D * D,
                                              wtl + (size_t)l * D * D, ybuf, N);
        if (l == 0) cudaStreamWaitEvent(0, evB, 0);   // CSR ready before agg1
        float* nxt = (l == 4) ? out : ((l & 1) ? fb : fa);
        float* thr = (l == 4) ? out_thr : nullptr;
        agg_kernel<<<agrid, TB>>>(ybuf, B[l], nxt, thr, N);
        cur = nxt;
    }
}

// round 7
// speedup vs baseline: 1.1032x; 1.1032x over previous
#include <cuda_runtime.h>
#include <math.h>
#include <stdint.h>

#define NMAX 50000
#define EMAX 800000
#define D    128
#define SAP  68            // A smem row pad (floats)

// ---------------- scratch (static device globals; no allocation) -------------
__device__ int   g_deg_out[NMAX];
__device__ int   g_deg_in [NMAX];
__device__ float g_ns[NMAX];
__device__ float g_nd[NMAX];
__device__ int   g_row_off[NMAX + 1];
__device__ int   g_cursor[NMAX];
__device__ int   g_csr_src[EMAX];
__device__ int   g_bsum[256];
__device__ int   g_boff[256];
__device__ int   g_total;
__device__ float g_y [NMAX * D];        // post-GEMM features (gather source)
__device__ float g_fa[NMAX * D];        // ping
__device__ float g_fb[NMAX * D];        // pong
// W^T in mma.sync B-fragment-major order: [kk(16)][nb(16)][lane(32)][2]
__device__ float g_wt_hi[5 * D * D];
__device__ float g_wt_lo[5 * D * D];

// ---------------- helpers ------------------------------------------------------
__device__ __forceinline__ float to_tf32(float x) {
    uint32_t u;
    asm("cvt.rna.tf32.f32 %0, %1;" : "=r"(u) : "f"(x));
    return __uint_as_float(u);
}

#define MMA_TF32(c, a, b0, b1)                                                  \
    asm volatile("mma.sync.aligned.m16n8k8.row.col.f32.tf32.tf32.f32 "          \
        "{%0,%1,%2,%3}, {%4,%5,%6,%7}, {%8,%9}, {%0,%1,%2,%3};"                 \
        : "+f"((c)[0]), "+f"((c)[1]), "+f"((c)[2]), "+f"((c)[3])                 \
        : "r"((a)[0]), "r"((a)[1]), "r"((a)[2]), "r"((a)[3]),                    \
          "r"(b0), "r"(b1))

// ---------------- graph preprocessing ----------------------------------------
__global__ void zero_kernel(int n) {
    int i = blockIdx.x * blockDim.x + threadIdx.x;
    if (i < n) { g_deg_out[i] = 0; g_deg_in[i] = 0; g_cursor[i] = 0; }
}

__global__ void count_kernel(const int* __restrict__ src,
                             const int* __restrict__ dst, int e) {
    int i = blockIdx.x * blockDim.x + threadIdx.x;
    if (i < e) {
        atomicAdd(&g_deg_out[src[i]], 1);
        atomicAdd(&g_deg_in [dst[i]], 1);
    }
}

__global__ void norm_kernel(int n) {
    int i = blockIdx.x * blockDim.x + threadIdx.x;
    if (i < n) {
        int dof = g_deg_out[i]; if (dof < 1) dof = 1;
        int din = g_deg_in [i]; if (din < 1) din = 1;
        g_ns[i] = rsqrtf((float)dof);
        g_nd[i] = rsqrtf((float)din);
    }
}

__global__ void scan1_kernel(int n) {
    int tid = threadIdx.x, lane = tid & 31, warp = tid >> 5;
    int i = blockIdx.x * 256 + tid;
    int v = (i < n) ? g_deg_in[i] : 0;
    int x = v;
    #pragma unroll
    for (int off = 1; off < 32; off <<= 1) {
        int t = __shfl_up_sync(0xffffffffu, x, off);
        if (lane >= off) x += t;
    }
    __shared__ int ws[8];
    if (lane == 31) ws[warp] = x;
    __syncthreads();
    if (tid == 0) {
        int c = 0;
        #pragma unroll
        for (int j = 0; j < 8; j++) { int t = ws[j]; ws[j] = c; c += t; }
        g_bsum[blockIdx.x] = c;
    }
    __syncthreads();
    if (i < n) g_row_off[i] = ws[warp] + x - v;
}

__global__ void scan2_kernel(int nb) {
    int tid = threadIdx.x, lane = tid & 31, warp = tid >> 5;
    int v = (tid < nb) ? g_bsum[tid] : 0;
    int x = v;
    #pragma unroll
    for (int off = 1; off < 32; off <<= 1) {
        int t = __shfl_up_sync(0xffffffffu, x, off);
        if (lane >= off) x += t;
    }
    __shared__ int ws[8];
    if (lane == 31) ws[warp] = x;
    __syncthreads();
    if (tid == 0) {
        int c = 0;
        #pragma unroll
        for (int j = 0; j < 8; j++) { int t = ws[j]; ws[j] = c; c += t; }
        g_total = c;
    }
    __syncthreads();
    if (tid < nb) g_boff[tid] = ws[warp] + x - v;
}

__global__ void scan3_kernel(int n) {
    int i = blockIdx.x * blockDim.x + threadIdx.x;
    if (i < n)       g_row_off[i] += g_boff[i >> 8];
    else if (i == n) g_row_off[n]  = g_total;
}

__global__ void fill_kernel(const int* __restrict__ src,
                            const int* __restrict__ dst, int e) {
    int i = blockIdx.x * blockDim.x + threadIdx.x;
    if (i < e) {
        int d = dst[i];
        int pos = g_row_off[d] + atomicAdd(&g_cursor[d], 1);
        g_csr_src[pos] = src[i];
    }
}

__global__ void sort_kernel(int n) {
    int i = blockIdx.x * blockDim.x + threadIdx.x;
    if (i >= n) return;
    int a = g_row_off[i], b = g_row_off[i + 1];
    for (int p = a + 1; p < b; p++) {
        int key = g_csr_src[p];
        int q = p - 1;
        while (q >= a && g_csr_src[q] > key) { g_csr_src[q + 1] = g_csr_src[q]; q--; }
        g_csr_src[q + 1] = key;
    }
}

// ------- W^T split to tf32 hi/lo AND permuted to B-fragment order -------------
__global__ void wprep_kernel(const float* __restrict__ W0, const float* __restrict__ W1,
                             const float* __restrict__ W2, const float* __restrict__ W3,
                             const float* __restrict__ W4) {
    const float* Ws[5] = {W0, W1, W2, W3, W4};
    const float* W = Ws[blockIdx.z];
    __shared__ float t[32][33];
    int kb = blockIdx.x * 32, nb0 = blockIdx.y * 32;
    int tx = threadIdx.x, ty = threadIdx.y;
    #pragma unroll
    for (int j = 0; j < 4; j++)
        t[ty + 8 * j][tx] = W[(kb + ty + 8 * j) * D + nb0 + tx];
    __syncthreads();
    size_t base = (size_t)blockIdx.z * D * D;
    #pragma unroll
    for (int j = 0; j < 4; j++) {
        int ncol = nb0 + ty + 8 * j;
        int krow = kb + tx;
        float v = t[tx][ty + 8 * j];       // = W^T[ncol][krow]
        float hi = to_tf32(v);
        int nbk = ncol >> 3, g = ncol & 7;
        int kk = krow >> 3, tt = krow & 7;
        int tq = tt & 3, jj = tt >> 2;
        int lane = (g << 2) | tq;
        size_t fidx = base + (size_t)(((kk * 16 + nbk) * 32 + lane) * 2 + jj);
        g_wt_hi[fidx] = hi;
        g_wt_lo[fidx] = v - hi;
    }
}

// ---------------- tensor-core GEMM via mma.sync (3xTF32) ----------------------
__global__ __launch_bounds__(256, 1)
void gemm_mma_kernel(const float* __restrict__ x,
                     const float* __restrict__ wth,
                     const float* __restrict__ wtl,
                     float* __restrict__ y, int n) {
    extern __shared__ float sm[];
    float* sWh = sm;                       // 16384 floats
    float* sWl = sm + 16384;
    float* sAh = sm + 32768;               // 128*68 = 8704
    float* sAl = sm + 32768 + 8704;

    int tid = threadIdx.x;
    for (int idx = tid; idx < 4096; idx += 256) {
        *(float4*)(sWh + idx * 4) = *(const float4*)(wth + (size_t)idx * 4);
        *(float4*)(sWl + idx * 4) = *(const float4*)(wtl + (size_t)idx * 4);
    }

    int lane = tid & 31, wid = tid >> 5;
    int wm = wid & 3;
    int wn = wid >> 2;
    int g = lane >> 2, t = lane & 3;

    int prow[8], pq[8];
    #pragma unroll
    for (int j = 0; j < 8; j++) {
        int idx = tid + 256 * j;
        prow[j] = idx >> 4;
        pq[j]   = (idx & 15) * 4;
    }

    int ntiles = (n + 127) >> 7;

    for (int tile = blockIdx.x; tile < ntiles; tile += gridDim.x) {
        int r0 = tile << 7;
        float acc[2][8][4];
        #pragma unroll
        for (int mt = 0; mt < 2; mt++)
            #pragma unroll
            for (int nt = 0; nt < 8; nt++)
                #pragma unroll
                for (int j = 0; j < 4; j++) acc[mt][nt][j] = 0.f;

        float4 pf[8];
        #pragma unroll
        for (int j = 0; j < 8; j++) {
            int gr = r0 + prow[j];
            pf[j] = (gr < n) ? *(const float4*)(x + (size_t)gr * D + pq[j])
                             : make_float4(0.f, 0.f, 0.f, 0.f);
        }

        #pragma unroll
        for (int c = 0; c < 2; c++) {
            __syncthreads();
            #pragma unroll
            for (int j = 0; j < 8; j++) {
                int gr = r0 + prow[j];
                float s = (gr < n) ? g_ns[gr] : 0.f;
                float4 v = pf[j];
                v.x *= s; v.y *= s; v.z *= s; v.w *= s;
                float4 h, l;
                h.x = to_tf32(v.x); l.x = v.x - h.x;
                h.y = to_tf32(v.y); l.y = v.y - h.y;
                h.z = to_tf32(v.z); l.z = v.z - h.z;
                h.w = to_tf32(v.w); l.w = v.w - h.w;
                *(float4*)(sAh + prow[j] * SAP + pq[j]) = h;
                *(float4*)(sAl + prow[j] * SAP + pq[j]) = l;
            }
            if (c == 0) {
                #pragma unroll
                for (int j = 0; j < 8; j++) {
                    int gr = r0 + prow[j];
                    pf[j] = (gr < n) ? *(const float4*)(x + (size_t)gr * D + 64 + pq[j])
                                     : make_float4(0.f, 0.f, 0.f, 0.f);
                }
            }
            __syncthreads();

            #pragma unroll
            for (int ks = 0; ks < 8; ks++) {
                int kA = ks * 8;
                int kk = c * 8 + ks;
                uint32_t ah[2][4], al[2][4];
                #pragma unroll
                for (int mt = 0; mt < 2; mt++) {
                    int rb = wm * 32 + mt * 16;
                    int i00 = (rb + g) * SAP + kA + t;
                    int i10 = (rb + g + 8) * SAP + kA + t;
                    ah[mt][0] = __float_as_uint(sAh[i00]);
                    ah[mt][1] = __float_as_uint(sAh[i10]);
                    ah[mt][2] = __float_as_uint(sAh[i00 + 4]);
                    ah[mt][3] = __float_as_uint(sAh[i10 + 4]);
                    al[mt][0] = __float_as_uint(sAl[i00]);
                    al[mt][1] = __float_as_uint(sAl[i10]);
                    al[mt][2] = __float_as_uint(sAl[i00 + 4]);
                    al[mt][3] = __float_as_uint(sAl[i10 + 4]);
                }
                int fb = ((kk * 16 + wn * 8) * 32 + lane) * 2;
                #pragma unroll
                for (int nt = 0; nt < 8; nt++) {
                    uint2 bh = *(const uint2*)(sWh + fb + nt * 64);
                    uint2 bl = *(const uint2*)(sWl + fb + nt * 64);
                    #pragma unroll
                    for (int mt = 0; mt < 2; mt++) {
                        MMA_TF32(acc[mt][nt], ah[mt], bh.x, bh.y);
                        MMA_TF32(acc[mt][nt], ah[mt], bl.x, bl.y);
                        MMA_TF32(acc[mt][nt], al[mt], bh.x, bh.y);
                    }
                }
            }
        }

        #pragma unroll
        for (int mt = 0; mt < 2; mt++) {
            int rlo = r0 + wm * 32 + mt * 16 + g;
            int rhi = rlo + 8;
            #pragma unroll
            for (int nt = 0; nt < 8; nt++) {
                int cb = wn * 64 + nt * 8 + 2 * t;
                if (rlo < n) {
                    float2 o = {acc[mt][nt][0], acc[mt][nt][1]};
                    *(float2*)(y + (size_t)rlo * D + cb) = o;
                }
                if (rhi < n) {
                    float2 o = {acc[mt][nt][2], acc[mt][nt][3]};
                    *(float2*)(y + (size_t)rhi * D + cb) = o;
                }
            }
        }
    }
}

// ---------------- aggregation: out = relu(nd * segsum(y[src]) + b) -----------
// 1 warp per node; lane handles 4 contiguous cols (float4). (round-5 form)
__global__ void agg_kernel(const float* __restrict__ y,
                           const float* __restrict__ bias,
                           float* __restrict__ out,
                           float* __restrict__ out_thr, int n) {
    int gw = (blockIdx.x * blockDim.x + threadIdx.x) >> 5;
    int lane = threadIdx.x & 31;
    if (gw >= n) return;
    int s0 = g_row_off[gw], s1 = g_row_off[gw + 1];
    float4 acc = {0, 0, 0, 0};
    int e = s0;
    for (; e + 4 <= s1; e += 4) {
        int i0 = g_csr_src[e + 0];
        int i1 = g_csr_src[e + 1];
        int i2 = g_csr_src[e + 2];
        int i3 = g_csr_src[e + 3];
        float4 v0 = *(const float4*)(y + (size_t)i0 * D + lane * 4);
        float4 v1 = *(const float4*)(y + (size_t)i1 * D + lane * 4);
        float4 v2 = *(const float4*)(y + (size_t)i2 * D + lane * 4);
        float4 v3 = *(const float4*)(y + (size_t)i3 * D + lane * 4);
        acc.x += v0.x + v1.x + v2.x + v3.x;
        acc.y += v0.y + v1.y + v2.y + v3.y;
        acc.z += v0.z + v1.z + v2.z + v3.z;
        acc.w += v0.w + v1.w + v2.w + v3.w;
    }
    for (; e < s1; e++) {
        int i0 = g_csr_src[e];
        float4 v0 = *(const float4*)(y + (size_t)i0 * D + lane * 4);
        acc.x += v0.x; acc.y += v0.y; acc.z += v0.z; acc.w += v0.w;
    }
    float ndv = g_nd[gw];
    float4 bb = *(const float4*)(bias + lane * 4);
    float4 r;
    r.x = fmaxf(acc.x * ndv + bb.x, 0.f);
    r.y = fmaxf(acc.y * ndv + bb.y, 0.f);
    r.z = fmaxf(acc.z * ndv + bb.z, 0.f);
    r.w = fmaxf(acc.w * ndv + bb.w, 0.f);
    *(float4*)(out + (size_t)gw * D + lane * 4) = r;
    if (out_thr) {
        float4 t;
        t.x = r.x >= 0.5f ? 1.f : 0.f;
        t.y = r.y >= 0.5f ? 1.f : 0.f;
        t.z = r.z >= 0.5f ? 1.f : 0.f;
        t.w = r.w >= 0.5f ? 1.f : 0.f;
        *(float4*)(out_thr + (size_t)gw * D + lane * 4) = t;
    }
}

// ---------------- host launcher ----------------------------------------------
extern "C" void kernel_launch(void* const* d_in, const int* in_sizes, int n_in,
                              void* d_out, int out_size) {
    const float* in_feat = (const float*)d_in[0];
    const int*   src     = (const int*)d_in[1];
    const int*   dst     = (const int*)d_in[2];
    int N = in_sizes[0] / D;
    int E = in_sizes[1];

    const float* W[5]; const float* B[5];
    int nw = 0, nb = 0;
    for (int i = 3; i < n_in; i++) {
        if (in_sizes[i] >= D * D) { if (nw < 5) W[nw++] = (const float*)d_in[i]; }
        else                      { if (nb < 5) B[nb++] = (const float*)d_in[i]; }
    }

    float* out = (float*)d_out;
    float* out_thr = (out_size >= 2 * N * D) ? out + (size_t)N * D : nullptr;

    float* fa; float* fb; float* ybuf; float* wth; float* wtl;
    cudaGetSymbolAddress((void**)&fa,   g_fa);
    cudaGetSymbolAddress((void**)&fb,   g_fb);
    cudaGetSymbolAddress((void**)&ybuf, g_y);
    cudaGetSymbolAddress((void**)&wth,  g_wt_hi);
    cudaGetSymbolAddress((void**)&wtl,  g_wt_lo);

    static cudaStream_t s2 = nullptr;
    static cudaEvent_t evA = nullptr, evB = nullptr;
    if (!s2) {
        cudaStreamCreateWithFlags(&s2, cudaStreamNonBlocking);
        cudaEventCreateWithFlags(&evA, cudaEventDisableTiming);
        cudaEventCreateWithFlags(&evB, cudaEventDisableTiming);
    }

    const int TB = 256;
    int nb_nodes = (N + TB - 1) / TB;
    int nb_edges = (E + TB - 1) / TB;
    int nscan = nb_nodes;

    zero_kernel <<<nb_nodes, TB>>>(N);
    count_kernel<<<nb_edges, TB>>>(src, dst, E);
    cudaEventRecord(evA, 0);

    cudaStreamWaitEvent(s2, evA, 0);
    scan1_kernel<<<nscan, 256, 0, s2>>>(N);
    scan2_kernel<<<1, 256, 0, s2>>>(nscan);
    scan3_kernel<<<(N + 1 + TB - 1) / TB, TB, 0, s2>>>(N);
    fill_kernel <<<nb_edges, TB, 0, s2>>>(src, dst, E);
    sort_kernel <<<nb_nodes, TB, 0, s2>>>(N);
    cudaEventRecord(evB, s2);

    norm_kernel <<<nb_nodes, TB>>>(N);
    wprep_kernel<<<dim3(4, 4, 5), dim3(32, 8)>>>(W[0], W[1], W[2], W[3], W[4]);

    size_t smem = (size_t)(32768 + 2 * D * SAP) * sizeof(float);
    cudaFuncSetAttribute(gemm_mma_kernel,
                         cudaFuncAttributeMaxDynamicSharedMemorySize, (int)smem);
    int ntiles = (N + 127) / 128;
    int ggrid = 148;
    if (ggrid > ntiles) ggrid = ntiles;
    int agrid = (N * 32 + TB - 1) / TB;   // 1 warp per node

    const float* cur = in_feat;
    for (int l = 0; l < 5; l++) {
        gemm_mma_kernel<<<ggrid, 256, smem>>>(cur, wth + (size_t)l * D * D,
                                              wtl + (size_t)l * D * D, ybuf, N);
        if (l == 0) cudaStreamWaitEvent(0, evB, 0);   // CSR ready before agg1
        float* nxt = (l == 4) ? out : ((l & 1) ? fb : fa);
        float* thr = (l == 4) ? out_thr : nullptr;
        agg_kernel<<<agrid, TB>>>(ybuf, B[l], nxt, thr, N);
        cur = nxt;
    }
}